// round 10
// baseline (speedup 1.0000x reference)
#include <cuda_runtime.h>
#include <cuda_bf16.h>
#include <cuda_fp16.h>
#include <mma.h>
#include <float.h>

using namespace nvcuda;

// Problem constants (fixed by reference setup_inputs)
#define LN   1024      // sequence length L
#define DD   768       // hidden d
#define HH   12        // heads
#define EE   32        // entities
#define MM   4         // mentions
#define RR   256       // relations per doc
#define NMAX 4         // batch

// Scratch (device globals -- no allocation allowed)
__device__ float g_e_emb[NMAX * EE * DD];                        // (n,E,d)
__device__ __align__(16) __half g_e_att[NMAX * EE * HH * LN];    // (n,E,h,L) fp16

// split-bf16 operands for the rs GEMM
__device__ __align__(16) __nv_bfloat16 g_A_hi[NMAX * RR * LN];   // ht_att hi
__device__ __align__(16) __nv_bfloat16 g_A_lo[NMAX * RR * LN];   // ht_att lo
__device__ __align__(16) __nv_bfloat16 g_B_hi[NMAX * LN * DD];   // seq hi
__device__ __align__(16) __nv_bfloat16 g_B_lo[NMAX * LN * DD];   // seq lo

// ---------------------------------------------------------------------------
// split helper: float4 -> 4 hi bf16 (uint2) + 4 lo bf16 (uint2)
// ---------------------------------------------------------------------------
__device__ __forceinline__ void split4(float4 v, uint2& uh, uint2& ul)
{
    __nv_bfloat162 h01 = __float22bfloat162_rn(make_float2(v.x, v.y));
    __nv_bfloat162 h23 = __float22bfloat162_rn(make_float2(v.z, v.w));
    float2 f01 = __bfloat1622float2(h01);
    float2 f23 = __bfloat1622float2(h23);
    __nv_bfloat162 l01 = __float22bfloat162_rn(make_float2(v.x - f01.x, v.y - f01.y));
    __nv_bfloat162 l23 = __float22bfloat162_rn(make_float2(v.z - f23.x, v.w - f23.y));
    uh.x = *(unsigned*)&h01; uh.y = *(unsigned*)&h23;
    ul.x = *(unsigned*)&l01; ul.y = *(unsigned*)&l23;
}

// ---------------------------------------------------------------------------
// Fused pre-kernel: e_emb | split_seq | e_att(fp16), by blockIdx range.
// split & e_att sections process TWO elements per thread for MLP.
// ---------------------------------------------------------------------------
#define NB_EMB   ((NMAX * EE * DD) / 256)                   // 384
#define NB_SPL   ((NMAX * LN * DD / 4) / 2 / 256)           // 1536
#define NB_EATT  ((NMAX * EE * HH * (LN / 4)) / 2 / 256)    // 768

__global__ void k_pre(const float* __restrict__ seq,
                      const float* __restrict__ att,
                      const int*   __restrict__ pos,
                      const float* __restrict__ mask,
                      int n)
{
    int blk = blockIdx.x;
    if (blk < NB_EMB) {
        // ---- e_emb ----
        int idx = blk * 256 + threadIdx.x;
        int total = n * EE * DD;
        if (idx >= total) return;
        int k = idx % DD;
        int e = (idx / DD) % EE;
        int i = idx / (DD * EE);
        const int*   p  = pos  + (i * EE + e) * MM;
        const float* mk = mask + (i * EE + e) * MM;
        float v[MM];
        float mx = -FLT_MAX;
#pragma unroll
        for (int m = 0; m < MM; m++) {
            int pp = p[m] + 1;                       // OFFSET
            float x = seq[(i * LN + pp) * DD + k];
            if (mk[m] <= 0.0f) x = -FLT_MAX;
            v[m] = x;
            mx = fmaxf(mx, x);
        }
        float s = 0.0f;
#pragma unroll
        for (int m = 0; m < MM; m++) s += expf(v[m] - mx);
        g_e_emb[idx] = mx + logf(s);
    } else if (blk < NB_EMB + NB_SPL) {
        // ---- split seq into bf16 hi/lo (2 float4 per thread) ----
        int half = n * LN * DD / 4 / 2;
        int idx = (blk - NB_EMB) * 256 + threadIdx.x;
        if (idx >= half) return;
        float4 v0 = ((const float4*)seq)[idx];
        float4 v1 = ((const float4*)seq)[idx + half];
        uint2 uh, ul;
        split4(v0, uh, ul);
        ((uint2*)g_B_hi)[idx] = uh;
        ((uint2*)g_B_lo)[idx] = ul;
        split4(v1, uh, ul);
        ((uint2*)g_B_hi)[idx + half] = uh;
        ((uint2*)g_B_lo)[idx + half] = ul;
    } else {
        // ---- e_att -> fp16 (2 float4 -> 2 half4 per thread) ----
        int half_n = n * EE * HH * (LN / 4) / 2;
        int base = (blk - NB_EMB - NB_SPL) * 256 + threadIdx.x;
        if (base >= half_n) return;
#pragma unroll
        for (int u = 0; u < 2; u++) {
            int idx = base + u * half_n;
            int l4 = idx % (LN / 4);
            int hh = (idx / (LN / 4)) % HH;
            int e  = (idx / ((LN / 4) * HH)) % EE;
            int i  = idx / ((LN / 4) * HH * EE);
            const int*   p  = pos  + (i * EE + e) * MM;
            const float* mk = mask + (i * EE + e) * MM;
            const float4* att4 = (const float4*)att;
            float cnt = 0.0f;
            float4 s = make_float4(0.f, 0.f, 0.f, 0.f);
#pragma unroll
            for (int m = 0; m < MM; m++) {
                float mm = mk[m];
                cnt += mm;
                int pp = p[m] + 1;
                float4 a = att4[((size_t)(i * HH + hh) * LN + pp) * (LN / 4) + l4];
                s.x += mm * a.x; s.y += mm * a.y; s.z += mm * a.z; s.w += mm * a.w;
            }
            float inv = 1.0f / fmaxf(cnt, 1.0f);
            __half2 h01 = __floats2half2_rn(s.x * inv, s.y * inv);
            __half2 h23 = __floats2half2_rn(s.z * inv, s.w * inv);
            uint2 w;
            w.x = *(unsigned*)&h01;
            w.y = *(unsigned*)&h23;
            ((uint2*)g_e_att)[idx] = w;
        }
    }
}

// ---------------------------------------------------------------------------
// ht_att: one block (256 thr) per (i,r), fp16 inputs, fp32 math.
// ht[l] = (1/H) sum_h eA[h,l]*eB[h,l];  ht /= (sum_l ht + 1e-5)
// Writes SPLIT bf16 hi/lo A operand for the GEMM.
// ---------------------------------------------------------------------------
__global__ void k_ht_att(const int* __restrict__ hts, int n)
{
    int b = blockIdx.x;               // i*R + r
    int i = b / RR;
    int ha = hts[b * 2 + 0];
    int ta = hts[b * 2 + 1];

    const uint2* A = (const uint2*)(g_e_att + (size_t)(i * EE + ha) * HH * LN);
    const uint2* B = (const uint2*)(g_e_att + (size_t)(i * EE + ta) * HH * LN);
    int t = threadIdx.x;              // 256 threads, 4 l's each

    float4 s = make_float4(0.f, 0.f, 0.f, 0.f);
#pragma unroll
    for (int hh = 0; hh < HH; hh++) {
        uint2 ua = A[hh * (LN / 4) + t];
        uint2 ub = B[hh * (LN / 4) + t];
        float2 a01 = __half22float2(*(__half2*)&ua.x);
        float2 a23 = __half22float2(*(__half2*)&ua.y);
        float2 b01 = __half22float2(*(__half2*)&ub.x);
        float2 b23 = __half22float2(*(__half2*)&ub.y);
        s.x += a01.x * b01.x; s.y += a01.y * b01.y;
        s.z += a23.x * b23.x; s.w += a23.y * b23.y;
    }
    const float invH = 1.0f / (float)HH;
    s.x *= invH; s.y *= invH; s.z *= invH; s.w *= invH;
    float local = s.x + s.y + s.z + s.w;

    __shared__ float red[8];
#pragma unroll
    for (int off = 16; off > 0; off >>= 1)
        local += __shfl_xor_sync(0xffffffffu, local, off);
    if ((t & 31) == 0) red[t >> 5] = local;
    __syncthreads();
    if (t < 32) {
        float x = (t < 8) ? red[t] : 0.0f;
#pragma unroll
        for (int off = 4; off > 0; off >>= 1)
            x += __shfl_xor_sync(0xffffffffu, x, off);
        if (t == 0) red[0] = x;
    }
    __syncthreads();
    float inv = 1.0f / (red[0] + 1e-5f);

    float4 o = make_float4(s.x * inv, s.y * inv, s.z * inv, s.w * inv);
    uint2 uh, ul;
    split4(o, uh, ul);
    ((uint2*)(g_A_hi + (size_t)b * LN))[t] = uh;
    ((uint2*)(g_A_lo + (size_t)b * LN))[t] = ul;
}

// ---------------------------------------------------------------------------
// Kernel 4: rs plane GEMM on tensor cores, split-bf16 3-term compensation:
//   C = Ahi*Bhi + Ahi*Blo + Alo*Bhi   (fp32 accum)   [R8 proven config]
// Block 64(M) x 96(N), BK=32, 8 warps as 4(M) x 2(N) -> warp tile 16x48,
// term-outer mma order, double-buffered smem, register prefetch.
// grid = 8 x 4 x 4 = 128 blocks -> single wave. Fused hs/ts plane copy.
// ---------------------------------------------------------------------------
#define GBM 64
#define GBN 96
#define GBK 32
#define GT  256
#define LDA (GBK + 8)    // 40 bf16 row stride
#define LDB (GBN + 8)    // 104 bf16 row stride

__global__ __launch_bounds__(GT, 1) void k_gemm(const int* __restrict__ hts,
                                                float* __restrict__ out, int n)
{
    __shared__ __align__(16) __nv_bfloat16 Ah[2][GBM][LDA];
    __shared__ __align__(16) __nv_bfloat16 Al[2][GBM][LDA];
    __shared__ __align__(16) __nv_bfloat16 Bh[2][GBK][LDB];
    __shared__ __align__(16) __nv_bfloat16 Bl[2][GBK][LDB];

    int i = blockIdx.z;
    const __nv_bfloat16* Adh = g_A_hi + (size_t)i * RR * LN;
    const __nv_bfloat16* Adl = g_A_lo + (size_t)i * RR * LN;
    const __nv_bfloat16* Bdh = g_B_hi + (size_t)i * LN * DD;
    const __nv_bfloat16* Bdl = g_B_lo + (size_t)i * LN * DD;
    size_t P = (size_t)n * RR * DD;
    float* Cd = out + 2 * P + (size_t)i * RR * DD;      // R x D

    int rowBase = blockIdx.y * GBM;
    int colBase = blockIdx.x * GBN;
    int tid = threadIdx.x;
    int w   = tid >> 5;
    int wm  = w & 3;          // 0..3 : M slice (16 rows)
    int wn  = w >> 2;         // 0..1 : N slice (48 cols)

    // ---- loader slots (uint4 = 8 bf16) ----
    int aRow = tid >> 2, aK8 = (tid & 3) * 8;
    int b0Row = tid / 12,         b0N = (tid % 12) * 8;
    int b1Row = (tid + 256) / 12, b1N = ((tid + 256) % 12) * 8;
    bool hasB1 = tid < 128;

    wmma::fragment<wmma::accumulator, 16, 16, 16, float> acc[3];
#pragma unroll
    for (int j = 0; j < 3; j++) wmma::fill_fragment(acc[j], 0.0f);

    // ---- initial global loads (k0 = 0) ----
    uint4 rah, ral, rbh0, rbl0, rbh1, rbl1;
    rah = *(const uint4*)&Adh[(size_t)(rowBase + aRow) * LN + aK8];
    ral = *(const uint4*)&Adl[(size_t)(rowBase + aRow) * LN + aK8];
    rbh0 = *(const uint4*)&Bdh[(size_t)b0Row * DD + colBase + b0N];
    rbl0 = *(const uint4*)&Bdl[(size_t)b0Row * DD + colBase + b0N];
    if (hasB1) {
        rbh1 = *(const uint4*)&Bdh[(size_t)b1Row * DD + colBase + b1N];
        rbl1 = *(const uint4*)&Bdl[(size_t)b1Row * DD + colBase + b1N];
    }

    int buf = 0;
    for (int k0 = 0; k0 < LN; k0 += GBK) {
        *(uint4*)&Ah[buf][aRow][aK8] = rah;
        *(uint4*)&Al[buf][aRow][aK8] = ral;
        *(uint4*)&Bh[buf][b0Row][b0N] = rbh0;
        *(uint4*)&Bl[buf][b0Row][b0N] = rbl0;
        if (hasB1) {
            *(uint4*)&Bh[buf][b1Row][b1N] = rbh1;
            *(uint4*)&Bl[buf][b1Row][b1N] = rbl1;
        }
        __syncthreads();

        int kn = k0 + GBK;
        if (kn < LN) {
            rah = *(const uint4*)&Adh[(size_t)(rowBase + aRow) * LN + kn + aK8];
            ral = *(const uint4*)&Adl[(size_t)(rowBase + aRow) * LN + kn + aK8];
            rbh0 = *(const uint4*)&Bdh[(size_t)(kn + b0Row) * DD + colBase + b0N];
            rbl0 = *(const uint4*)&Bdl[(size_t)(kn + b0Row) * DD + colBase + b0N];
            if (hasB1) {
                rbh1 = *(const uint4*)&Bdh[(size_t)(kn + b1Row) * DD + colBase + b1N];
                rbl1 = *(const uint4*)&Bdl[(size_t)(kn + b1Row) * DD + colBase + b1N];
            }
        }

#pragma unroll
        for (int kk = 0; kk < GBK / 16; kk++) {
            wmma::fragment<wmma::matrix_a, 16, 16, 16, __nv_bfloat16, wmma::row_major> fah, fal;
            wmma::fragment<wmma::matrix_b, 16, 16, 16, __nv_bfloat16, wmma::row_major> fbh[3], fbl[3];
            wmma::load_matrix_sync(fah, &Ah[buf][wm * 16][kk * 16], LDA);
            wmma::load_matrix_sync(fal, &Al[buf][wm * 16][kk * 16], LDA);
#pragma unroll
            for (int j = 0; j < 3; j++) {
                wmma::load_matrix_sync(fbh[j], &Bh[buf][kk * 16][wn * 48 + j * 16], LDB);
                wmma::load_matrix_sync(fbl[j], &Bl[buf][kk * 16][wn * 48 + j * 16], LDB);
            }
#pragma unroll
            for (int j = 0; j < 3; j++)
                wmma::mma_sync(acc[j], fah, fbh[j], acc[j]);
#pragma unroll
            for (int j = 0; j < 3; j++)
                wmma::mma_sync(acc[j], fah, fbl[j], acc[j]);
#pragma unroll
            for (int j = 0; j < 3; j++)
                wmma::mma_sync(acc[j], fal, fbh[j], acc[j]);
        }
        buf ^= 1;
        __syncthreads();
    }

    // ---- epilogue: store accumulators ----
#pragma unroll
    for (int j = 0; j < 3; j++) {
        float* c = &Cd[(size_t)(rowBase + wm * 16) * DD + colBase + wn * 48 + j * 16];
        wmma::store_matrix_sync(c, acc[j], DD, wmma::mem_row_major);
    }

    // ---- fused hs/ts plane copy for this block's (row, col) tile ----
    {
        const float4* emb4 = (const float4*)g_e_emb;
        float4* out4 = (float4*)out;
        size_t P4 = (size_t)n * RR * (DD / 4);
#pragma unroll
        for (int s = 0; s < 6; s++) {
            int idx = tid + s * GT;        // 0..1535
            int row = idx / 24;            // 0..63
            int c4  = idx % 24;
            int b = i * RR + rowBase + row;
            int ha = hts[b * 2 + 0];
            int ta = hts[b * 2 + 1];
            int col4 = colBase / 4 + c4;
            float4 vh = emb4[(size_t)(i * EE + ha) * (DD / 4) + col4];
            float4 vt = emb4[(size_t)(i * EE + ta) * (DD / 4) + col4];
            out4[(size_t)b * (DD / 4) + col4]      = vh;
            out4[P4 + (size_t)b * (DD / 4) + col4] = vt;
        }
    }
}

// ---------------------------------------------------------------------------
extern "C" void kernel_launch(void* const* d_in, const int* in_sizes, int n_in,
                              void* d_out, int out_size)
{
    const float* seq  = (const float*)d_in[0];   // (n, L, d)
    const float* att  = (const float*)d_in[1];   // (n, h, L, L)
    const int*   pos  = (const int*)  d_in[2];   // (n, E, M)
    const float* mask = (const float*)d_in[3];   // (n, E, M)
    const int*   hts  = (const int*)  d_in[4];   // (n, R, 2)
    float* out = (float*)d_out;

    int n = in_sizes[0] / (LN * DD);
    if (n > NMAX) n = NMAX;

    {   // fused e_emb + split_seq + e_att(fp16)
        k_pre<<<NB_EMB + NB_SPL + NB_EATT, 256>>>(seq, att, pos, mask, n);
    }
    {   // ht_att (fp16 in, writes split bf16 A)
        k_ht_att<<<n * RR, 256>>>(hts, n);
    }
    {   // rs plane GEMM (tensor cores, 8 warps, term-outer) + hs/ts copy
        dim3 grid(DD / GBN, RR / GBM, n);
        k_gemm<<<grid, GT>>>(hts, out, n);
    }
}

// round 11
// speedup vs baseline: 1.6769x; 1.6769x over previous
#include <cuda_runtime.h>
#include <cuda_fp16.h>
#include <mma.h>
#include <float.h>

using namespace nvcuda;

// Problem constants (fixed by reference setup_inputs)
#define LN   1024      // sequence length L
#define DD   768       // hidden d
#define HH   12        // heads
#define EE   32        // entities
#define MM   4         // mentions
#define RR   256       // relations per doc
#define NMAX 4         // batch

// Scratch (device globals -- no allocation allowed)
__device__ float g_e_emb[NMAX * EE * DD];                        // (n,E,d)
__device__ __align__(16) __half g_e_att[NMAX * EE * HH * LN];    // (n,E,h,L) fp16

// fp16 operands for the rs GEMM: A split hi/lo (exact), B hi only
__device__ __align__(16) __half g_A_hi[NMAX * RR * LN];   // ht_att hi
__device__ __align__(16) __half g_A_lo[NMAX * RR * LN];   // ht_att lo
__device__ __align__(16) __half g_B[NMAX * LN * DD];      // seq fp16

// ---------------------------------------------------------------------------
// fp16 split helper: float4 -> 4 hi (uint2) + 4 lo (uint2)
// ---------------------------------------------------------------------------
__device__ __forceinline__ void split4h(float4 v, uint2& uh, uint2& ul)
{
    __half2 h01 = __floats2half2_rn(v.x, v.y);
    __half2 h23 = __floats2half2_rn(v.z, v.w);
    float2 f01 = __half22float2(h01);
    float2 f23 = __half22float2(h23);
    __half2 l01 = __floats2half2_rn(v.x - f01.x, v.y - f01.y);
    __half2 l23 = __floats2half2_rn(v.z - f23.x, v.w - f23.y);
    uh.x = *(unsigned*)&h01; uh.y = *(unsigned*)&h23;
    ul.x = *(unsigned*)&l01; ul.y = *(unsigned*)&l23;
}

// ---------------------------------------------------------------------------
// Fused pre-kernel: e_emb | seq->fp16 | e_att(fp16), by blockIdx range.
// ---------------------------------------------------------------------------
#define NB_EMB   ((NMAX * EE * DD) / 256)                   // 384
#define NB_SPL   ((NMAX * LN * DD / 4) / 2 / 256)           // 1536
#define NB_EATT  ((NMAX * EE * HH * (LN / 4)) / 4 / 256)    // 384

__global__ void k_pre(const float* __restrict__ seq,
                      const float* __restrict__ att,
                      const int*   __restrict__ pos,
                      const float* __restrict__ mask,
                      int n)
{
    int blk = blockIdx.x;
    if (blk < NB_EMB) {
        // ---- e_emb ----
        int idx = blk * 256 + threadIdx.x;
        int total = n * EE * DD;
        if (idx >= total) return;
        int k = idx % DD;
        int e = (idx / DD) % EE;
        int i = idx / (DD * EE);
        const int*   p  = pos  + (i * EE + e) * MM;
        const float* mk = mask + (i * EE + e) * MM;
        float v[MM];
        float mx = -FLT_MAX;
#pragma unroll
        for (int m = 0; m < MM; m++) {
            int pp = p[m] + 1;                       // OFFSET
            float x = seq[(i * LN + pp) * DD + k];
            if (mk[m] <= 0.0f) x = -FLT_MAX;
            v[m] = x;
            mx = fmaxf(mx, x);
        }
        float s = 0.0f;
#pragma unroll
        for (int m = 0; m < MM; m++) s += expf(v[m] - mx);
        g_e_emb[idx] = mx + logf(s);
    } else if (blk < NB_EMB + NB_SPL) {
        // ---- seq -> fp16 (2 float4 per thread) ----
        int half_n = n * LN * DD / 4 / 2;
        int idx = (blk - NB_EMB) * 256 + threadIdx.x;
        if (idx >= half_n) return;
#pragma unroll
        for (int u = 0; u < 2; u++) {
            int id = idx + u * half_n;
            float4 v = ((const float4*)seq)[id];
            __half2 h01 = __floats2half2_rn(v.x, v.y);
            __half2 h23 = __floats2half2_rn(v.z, v.w);
            uint2 w;
            w.x = *(unsigned*)&h01;
            w.y = *(unsigned*)&h23;
            ((uint2*)g_B)[id] = w;
        }
    } else {
        // ---- e_att -> fp16 (4 float4 per thread for MLP) ----
        int q = n * EE * HH * (LN / 4) / 4;
        int base = (blk - NB_EMB - NB_SPL) * 256 + threadIdx.x;
        if (base >= q) return;
#pragma unroll
        for (int u = 0; u < 4; u++) {
            int idx = base + u * q;
            int l4 = idx % (LN / 4);
            int hh = (idx / (LN / 4)) % HH;
            int e  = (idx / ((LN / 4) * HH)) % EE;
            int i  = idx / ((LN / 4) * HH * EE);
            const int*   p  = pos  + (i * EE + e) * MM;
            const float* mk = mask + (i * EE + e) * MM;
            const float4* att4 = (const float4*)att;
            float cnt = 0.0f;
            float4 s = make_float4(0.f, 0.f, 0.f, 0.f);
#pragma unroll
            for (int m = 0; m < MM; m++) {
                float mm = mk[m];
                cnt += mm;
                int pp = p[m] + 1;
                float4 a = att4[((size_t)(i * HH + hh) * LN + pp) * (LN / 4) + l4];
                s.x += mm * a.x; s.y += mm * a.y; s.z += mm * a.z; s.w += mm * a.w;
            }
            float inv = 1.0f / fmaxf(cnt, 1.0f);
            __half2 h01 = __floats2half2_rn(s.x * inv, s.y * inv);
            __half2 h23 = __floats2half2_rn(s.z * inv, s.w * inv);
            uint2 w;
            w.x = *(unsigned*)&h01;
            w.y = *(unsigned*)&h23;
            ((uint2*)g_e_att)[idx] = w;
        }
    }
}

// ---------------------------------------------------------------------------
// ht_att: one block (256 thr) per (i,r), fp16 inputs, fp32 math.
// ht[l] = (1/H) sum_h eA[h,l]*eB[h,l];  ht /= (sum_l ht + 1e-5)
// Writes fp16 hi/lo A operand (exact split) for the GEMM.
// ---------------------------------------------------------------------------
__global__ void k_ht_att(const int* __restrict__ hts, int n)
{
    int b = blockIdx.x;               // i*R + r
    int i = b / RR;
    int ha = hts[b * 2 + 0];
    int ta = hts[b * 2 + 1];

    const uint2* A = (const uint2*)(g_e_att + (size_t)(i * EE + ha) * HH * LN);
    const uint2* B = (const uint2*)(g_e_att + (size_t)(i * EE + ta) * HH * LN);
    int t = threadIdx.x;              // 256 threads, 4 l's each

    float4 s = make_float4(0.f, 0.f, 0.f, 0.f);
#pragma unroll
    for (int hh = 0; hh < HH; hh++) {
        uint2 ua = A[hh * (LN / 4) + t];
        uint2 ub = B[hh * (LN / 4) + t];
        float2 a01 = __half22float2(*(__half2*)&ua.x);
        float2 a23 = __half22float2(*(__half2*)&ua.y);
        float2 b01 = __half22float2(*(__half2*)&ub.x);
        float2 b23 = __half22float2(*(__half2*)&ub.y);
        s.x += a01.x * b01.x; s.y += a01.y * b01.y;
        s.z += a23.x * b23.x; s.w += a23.y * b23.y;
    }
    const float invH = 1.0f / (float)HH;
    s.x *= invH; s.y *= invH; s.z *= invH; s.w *= invH;
    float local = s.x + s.y + s.z + s.w;

    __shared__ float red[8];
#pragma unroll
    for (int off = 16; off > 0; off >>= 1)
        local += __shfl_xor_sync(0xffffffffu, local, off);
    if ((t & 31) == 0) red[t >> 5] = local;
    __syncthreads();
    if (t < 32) {
        float x = (t < 8) ? red[t] : 0.0f;
#pragma unroll
        for (int off = 4; off > 0; off >>= 1)
            x += __shfl_xor_sync(0xffffffffu, x, off);
        if (t == 0) red[0] = x;
    }
    __syncthreads();
    float inv = 1.0f / (red[0] + 1e-5f);

    float4 o = make_float4(s.x * inv, s.y * inv, s.z * inv, s.w * inv);
    uint2 uh, ul;
    split4h(o, uh, ul);
    ((uint2*)(g_A_hi + (size_t)b * LN))[t] = uh;
    ((uint2*)(g_A_lo + (size_t)b * LN))[t] = ul;
}

// ---------------------------------------------------------------------------
// Kernel 4: rs plane GEMM on tensor cores, fp16 2-term compensation:
//   C = Ah*B + Al*B   (A exactly split to fp16 hi+lo; B fp16, residual
//   error ~2^-12 rms, incoherent over K=1024)
// Block 64(M) x 96(N), BK=32, 8 warps as 4(M) x 2(N) -> warp tile 16x48,
// term-outer mma (reuse distance 3), double-buffered smem, reg prefetch.
// grid = 8 x 4 x 4 = 128 blocks -> single wave. Fused hs/ts plane copy.
// ---------------------------------------------------------------------------
#define GBM 64
#define GBN 96
#define GBK 32
#define GT  256
#define LDA (GBK + 8)    // 40 halves
#define LDB (GBN + 8)    // 104 halves

__global__ __launch_bounds__(GT, 1) void k_gemm(const int* __restrict__ hts,
                                                float* __restrict__ out, int n)
{
    __shared__ __align__(16) __half Ah[2][GBM][LDA];
    __shared__ __align__(16) __half Al[2][GBM][LDA];
    __shared__ __align__(16) __half Bs[2][GBK][LDB];

    int i = blockIdx.z;
    const __half* Adh = g_A_hi + (size_t)i * RR * LN;
    const __half* Adl = g_A_lo + (size_t)i * RR * LN;
    const __half* Bd  = g_B    + (size_t)i * LN * DD;
    size_t P = (size_t)n * RR * DD;
    float* Cd = out + 2 * P + (size_t)i * RR * DD;      // R x D

    int rowBase = blockIdx.y * GBM;
    int colBase = blockIdx.x * GBN;
    int tid = threadIdx.x;
    int w   = tid >> 5;
    int wm  = w & 3;          // 0..3 : M slice (16 rows)
    int wn  = w >> 2;         // 0..1 : N slice (48 cols)

    // ---- loader slots (uint4 = 8 halves) ----
    int aRow = tid >> 2, aK8 = (tid & 3) * 8;                  // 256 slots/plane
    int b0Row = tid / 12,         b0N = (tid % 12) * 8;        // 384 slots
    int b1Row = (tid + 256) / 12, b1N = ((tid + 256) % 12) * 8;
    bool hasB1 = tid < 128;

    wmma::fragment<wmma::accumulator, 16, 16, 16, float> acc[3];
#pragma unroll
    for (int j = 0; j < 3; j++) wmma::fill_fragment(acc[j], 0.0f);

    // ---- initial global loads (k0 = 0) ----
    uint4 rah, ral, rb0, rb1;
    rah = *(const uint4*)&Adh[(size_t)(rowBase + aRow) * LN + aK8];
    ral = *(const uint4*)&Adl[(size_t)(rowBase + aRow) * LN + aK8];
    rb0 = *(const uint4*)&Bd[(size_t)b0Row * DD + colBase + b0N];
    if (hasB1) rb1 = *(const uint4*)&Bd[(size_t)b1Row * DD + colBase + b1N];

    int buf = 0;
    for (int k0 = 0; k0 < LN; k0 += GBK) {
        *(uint4*)&Ah[buf][aRow][aK8] = rah;
        *(uint4*)&Al[buf][aRow][aK8] = ral;
        *(uint4*)&Bs[buf][b0Row][b0N] = rb0;
        if (hasB1) *(uint4*)&Bs[buf][b1Row][b1N] = rb1;
        __syncthreads();

        int kn = k0 + GBK;
        if (kn < LN) {
            rah = *(const uint4*)&Adh[(size_t)(rowBase + aRow) * LN + kn + aK8];
            ral = *(const uint4*)&Adl[(size_t)(rowBase + aRow) * LN + kn + aK8];
            rb0 = *(const uint4*)&Bd[(size_t)(kn + b0Row) * DD + colBase + b0N];
            if (hasB1) rb1 = *(const uint4*)&Bd[(size_t)(kn + b1Row) * DD + colBase + b1N];
        }

#pragma unroll
        for (int kk = 0; kk < GBK / 16; kk++) {
            wmma::fragment<wmma::matrix_a, 16, 16, 16, __half, wmma::row_major> fah, fal;
            wmma::fragment<wmma::matrix_b, 16, 16, 16, __half, wmma::row_major> fb[3];
            wmma::load_matrix_sync(fah, &Ah[buf][wm * 16][kk * 16], LDA);
            wmma::load_matrix_sync(fal, &Al[buf][wm * 16][kk * 16], LDA);
#pragma unroll
            for (int j = 0; j < 3; j++)
                wmma::load_matrix_sync(fb[j], &Bs[buf][kk * 16][wn * 48 + j * 16], LDB);
            // term h (3 independent), then term l: reuse distance 3
#pragma unroll
            for (int j = 0; j < 3; j++)
                wmma::mma_sync(acc[j], fah, fb[j], acc[j]);
#pragma unroll
            for (int j = 0; j < 3; j++)
                wmma::mma_sync(acc[j], fal, fb[j], acc[j]);
        }
        buf ^= 1;
        __syncthreads();
    }

    // ---- epilogue: store accumulators ----
#pragma unroll
    for (int j = 0; j < 3; j++) {
        float* c = &Cd[(size_t)(rowBase + wm * 16) * DD + colBase + wn * 48 + j * 16];
        wmma::store_matrix_sync(c, acc[j], DD, wmma::mem_row_major);
    }

    // ---- fused hs/ts plane copy for this block's (row, col) tile ----
    {
        const float4* emb4 = (const float4*)g_e_emb;
        float4* out4 = (float4*)out;
        size_t P4 = (size_t)n * RR * (DD / 4);
#pragma unroll
        for (int s = 0; s < 6; s++) {
            int idx = tid + s * GT;        // 0..1535
            int row = idx / 24;            // 0..63
            int c4  = idx % 24;
            int b = i * RR + rowBase + row;
            int ha = hts[b * 2 + 0];
            int ta = hts[b * 2 + 1];
            int col4 = colBase / 4 + c4;
            float4 vh = emb4[(size_t)(i * EE + ha) * (DD / 4) + col4];
            float4 vt = emb4[(size_t)(i * EE + ta) * (DD / 4) + col4];
            out4[(size_t)b * (DD / 4) + col4]      = vh;
            out4[P4 + (size_t)b * (DD / 4) + col4] = vt;
        }
    }
}

// ---------------------------------------------------------------------------
extern "C" void kernel_launch(void* const* d_in, const int* in_sizes, int n_in,
                              void* d_out, int out_size)
{
    const float* seq  = (const float*)d_in[0];   // (n, L, d)
    const float* att  = (const float*)d_in[1];   // (n, h, L, L)
    const int*   pos  = (const int*)  d_in[2];   // (n, E, M)
    const float* mask = (const float*)d_in[3];   // (n, E, M)
    const int*   hts  = (const int*)  d_in[4];   // (n, R, 2)
    float* out = (float*)d_out;

    int n = in_sizes[0] / (LN * DD);
    if (n > NMAX) n = NMAX;

    {   // fused e_emb + seq->fp16 + e_att(fp16)
        k_pre<<<NB_EMB + NB_SPL + NB_EATT, 256>>>(seq, att, pos, mask, n);
    }
    {   // ht_att (fp16 in, writes fp16 hi/lo A)
        k_ht_att<<<n * RR, 256>>>(hts, n);
    }
    {   // rs plane GEMM (fp16 2-term, tensor cores) + hs/ts copy
        dim3 grid(DD / GBN, RR / GBM, n);
        k_gemm<<<grid, GT>>>(hts, out, n);
    }
}